// round 1
// baseline (speedup 1.0000x reference)
#include <cuda_runtime.h>
#include <cuda_bf16.h>
#include <math.h>

// ---------------- problem constants ----------------
#define SLEN 1024
#define BSZ  32
#define INDIM 512
#define H 8
#define D 64
#define NQKVB (H * (3 * D + 1))   // 1544
#define MROWS (SLEN * BSZ)        // 32768
#define NBH   (BSZ * H)           // 256
#define LN_EPS 1e-5f

// ---------------- scratch (static device globals; no allocation) ----------------
__device__ float g_h[(size_t)MROWS * INDIM];          // 64 MB
__device__ float g_qkvb[(size_t)MROWS * NQKVB];       // ~202 MB
__device__ float g_q[(size_t)NBH * SLEN * D];         // 64 MB
__device__ float g_k[(size_t)NBH * SLEN * D];         // 64 MB
__device__ float g_v[(size_t)NBH * SLEN * D];         // 64 MB
__device__ float g_beta[(size_t)NBH * SLEN];          // 1 MB
__device__ float g_o[(size_t)MROWS * INDIM];          // 64 MB

// ---------------- 1) LayerNorm ----------------
__global__ __launch_bounds__(256)
void ln_kernel(const float* __restrict__ x, const float* __restrict__ gamma,
               const float* __restrict__ beta)
{
    __shared__ float red[16];
    const int r = blockIdx.x;
    const int tid = threadIdx.x;
    const float* xr = x + (size_t)r * INDIM;
    float v0 = xr[tid];
    float v1 = xr[tid + 256];
    float s  = v0 + v1;
    float ss = v0 * v0 + v1 * v1;
    #pragma unroll
    for (int o = 16; o; o >>= 1) {
        s  += __shfl_xor_sync(0xFFFFFFFFu, s,  o);
        ss += __shfl_xor_sync(0xFFFFFFFFu, ss, o);
    }
    if ((tid & 31) == 0) { red[tid >> 5] = s; red[8 + (tid >> 5)] = ss; }
    __syncthreads();
    float st = 0.f, sst = 0.f;
    #pragma unroll
    for (int i = 0; i < 8; i++) { st += red[i]; sst += red[8 + i]; }
    const float mu  = st * (1.0f / INDIM);
    const float var = sst * (1.0f / INDIM) - mu * mu;
    const float inv = rsqrtf(var + LN_EPS);
    float* hr = g_h + (size_t)r * INDIM;
    hr[tid]       = (v0 - mu) * inv * gamma[tid]       + beta[tid];
    hr[tid + 256] = (v1 - mu) * inv * gamma[tid + 256] + beta[tid + 256];
}

// ---------------- 2/5) fp32 GEMM, 128x128x16 tiles, 8x8/thread ----------------
// mode 0: C = g_h @ B            (B = w_slow, N=1544) -> g_qkvb
// mode 1: C = g_o @ B + R        (B = w_out,  N=512, R = x) -> d_out
__global__ __launch_bounds__(256, 2)
void sgemm_kernel(const float* __restrict__ Bm, const float* __restrict__ R,
                  float* __restrict__ Cout, int N, int mode)
{
    __shared__ float As[2][16][132];
    __shared__ float Bs[2][16][128];

    const float* A = (mode == 0) ? g_h : g_o;
    float* C       = (mode == 0) ? g_qkvb : Cout;
    const int K = INDIM;

    const int tid = threadIdx.x;
    const int bm = blockIdx.y * 128;
    const int bn = blockIdx.x * 128;

    const int arow = tid >> 2;            // 0..63
    const int acol = (tid & 3) << 2;      // 0,4,8,12
    const int brow = tid >> 5;            // 0..7
    const int bcol = (tid & 31) << 2;     // 0..124

    const int ty = tid >> 4, tx = tid & 15;
    const int m0 = ty * 8, n0 = tx * 8;

    float acc[8][8];
    #pragma unroll
    for (int i = 0; i < 8; i++)
        #pragma unroll
        for (int j = 0; j < 8; j++) acc[i][j] = 0.f;

    const int nk = K >> 4;   // 32

    float4 a0, a1, b0, b1;
    // --- load tile 0 ---
    {
        const float* Ap = A + (size_t)(bm + arow) * K + acol;
        a0 = *(const float4*)Ap;
        a1 = *(const float4*)(Ap + (size_t)64 * K);
        const int col = bn + bcol;
        if (col < N) {
            const float* Bp = Bm + (size_t)brow * N + col;
            b0 = *(const float4*)Bp;
            b1 = *(const float4*)(Bp + (size_t)8 * N);
        } else { b0 = make_float4(0,0,0,0); b1 = b0; }
        As[0][acol + 0][arow] = a0.x; As[0][acol + 1][arow] = a0.y;
        As[0][acol + 2][arow] = a0.z; As[0][acol + 3][arow] = a0.w;
        As[0][acol + 0][arow + 64] = a1.x; As[0][acol + 1][arow + 64] = a1.y;
        As[0][acol + 2][arow + 64] = a1.z; As[0][acol + 3][arow + 64] = a1.w;
        *(float4*)&Bs[0][brow][bcol] = b0;
        *(float4*)&Bs[0][brow + 8][bcol] = b1;
    }
    __syncthreads();

    for (int kt = 0; kt < nk; kt++) {
        const int buf = kt & 1;
        const bool more = (kt + 1 < nk);
        if (more) {
            const int k0 = (kt + 1) << 4;
            const float* Ap = A + (size_t)(bm + arow) * K + k0 + acol;
            a0 = *(const float4*)Ap;
            a1 = *(const float4*)(Ap + (size_t)64 * K);
            const int col = bn + bcol;
            if (col < N) {
                const float* Bp = Bm + (size_t)(k0 + brow) * N + col;
                b0 = *(const float4*)Bp;
                b1 = *(const float4*)(Bp + (size_t)8 * N);
            } else { b0 = make_float4(0,0,0,0); b1 = b0; }
        }
        #pragma unroll
        for (int kk = 0; kk < 16; kk++) {
            float af[8], bf[8];
            *(float4*)&af[0] = *(const float4*)&As[buf][kk][m0];
            *(float4*)&af[4] = *(const float4*)&As[buf][kk][m0 + 4];
            *(float4*)&bf[0] = *(const float4*)&Bs[buf][kk][n0];
            *(float4*)&bf[4] = *(const float4*)&Bs[buf][kk][n0 + 4];
            #pragma unroll
            for (int i = 0; i < 8; i++)
                #pragma unroll
                for (int j = 0; j < 8; j++)
                    acc[i][j] += af[i] * bf[j];
        }
        if (more) {
            const int nb = buf ^ 1;
            As[nb][acol + 0][arow] = a0.x; As[nb][acol + 1][arow] = a0.y;
            As[nb][acol + 2][arow] = a0.z; As[nb][acol + 3][arow] = a0.w;
            As[nb][acol + 0][arow + 64] = a1.x; As[nb][acol + 1][arow + 64] = a1.y;
            As[nb][acol + 2][arow + 64] = a1.z; As[nb][acol + 3][arow + 64] = a1.w;
            *(float4*)&Bs[nb][brow][bcol] = b0;
            *(float4*)&Bs[nb][brow + 8][bcol] = b1;
            __syncthreads();
        }
    }

    // epilogue
    #pragma unroll
    for (int i = 0; i < 8; i++) {
        const int row = bm + m0 + i;
        float* Cr = C + (size_t)row * N;
        const float* Rr = R + (size_t)row * N;   // only used if mode==1
        #pragma unroll
        for (int j0 = 0; j0 < 8; j0 += 4) {
            const int col = bn + n0 + j0;
            if (col < N) {
                float4 v = make_float4(acc[i][j0], acc[i][j0+1], acc[i][j0+2], acc[i][j0+3]);
                if (mode == 1) {
                    float4 rv = *(const float4*)&Rr[col];
                    v.x += rv.x; v.y += rv.y; v.z += rv.z; v.w += rv.w;
                }
                *(float4*)&Cr[col] = v;
            }
        }
    }
}

// ---------------- 3) activation + relayout ----------------
__device__ __forceinline__ float elu_p1(float x) {
    return x > 0.f ? x + 1.0f : expf(x);
}

__global__ __launch_bounds__(256)
void act_kernel()
{
    const int r = blockIdx.x;            // 0..32767 = t*32+b
    const int w = threadIdx.x >> 5;      // head 0..7
    const int lane = threadIdx.x & 31;
    const int t = r >> 5, b = r & 31;
    const int bh = b * H + w;
    const float* p = g_qkvb + (size_t)r * NQKVB + w * (3 * D + 1);
    const size_t ob = ((size_t)bh * SLEN + t) * D;

    // q
    float q0 = elu_p1(p[lane]);
    float q1 = elu_p1(p[lane + 32]);
    float s = q0 + q1;
    #pragma unroll
    for (int o = 16; o; o >>= 1) s += __shfl_xor_sync(0xFFFFFFFFu, s, o);
    float inv = 1.0f / s;
    g_q[ob + lane] = q0 * inv;
    g_q[ob + lane + 32] = q1 * inv;
    // k
    float k0 = elu_p1(p[D + lane]);
    float k1 = elu_p1(p[D + lane + 32]);
    s = k0 + k1;
    #pragma unroll
    for (int o = 16; o; o >>= 1) s += __shfl_xor_sync(0xFFFFFFFFu, s, o);
    inv = 1.0f / s;
    g_k[ob + lane] = k0 * inv;
    g_k[ob + lane + 32] = k1 * inv;
    // v (copy / relayout)
    g_v[ob + lane] = p[2 * D + lane];
    g_v[ob + lane + 32] = p[2 * D + lane + 32];
    // beta
    if (lane == 0)
        g_beta[(size_t)bh * SLEN + t] = 1.0f / (1.0f + expf(-p[3 * D]));
}

// ---------------- 4) delta-rule scan ----------------
// one CTA per (b,h); W[64][64] in registers: thread (row=tid>>2) owns 16 cols.
__global__ __launch_bounds__(256)
void scan_kernel()
{
    const int bh = blockIdx.x;
    const int b = bh >> 3, h = bh & 7;
    const int tid = threadIdx.x;
    const int row = tid >> 2;
    const int c0 = (tid & 3) << 4;

    __shared__ float sk[D], sv[D], sq[D], sb[1];

    float W[16];
    #pragma unroll
    for (int j = 0; j < 16; j++) W[j] = 0.f;

    const size_t base0 = (size_t)bh * SLEN * D;

    for (int t = 0; t < SLEN; t++) {
        const size_t base = base0 + (size_t)t * D;
        if (tid < D)            sk[tid]       = g_k[base + tid];
        else if (tid < 2 * D)   sv[tid - D]   = g_v[base + tid - D];
        else if (tid < 3 * D)   sq[tid - 2*D] = g_q[base + tid - 2*D];
        else if (tid == 3 * D)  sb[0]         = g_beta[(size_t)bh * SLEN + t];
        __syncthreads();

        // v_old[row] = sum_j W[row][j] * k[j]
        float vold = 0.f;
        #pragma unroll
        for (int j = 0; j < 16; j++) vold += W[j] * sk[c0 + j];
        vold += __shfl_xor_sync(0xFFFFFFFFu, vold, 1);
        vold += __shfl_xor_sync(0xFFFFFFFFu, vold, 2);

        const float upd = sb[0] * (sv[row] - vold);

        // W += upd * k^T ; o[row] = sum_j W[row][j] * q[j]
        float op = 0.f;
        #pragma unroll
        for (int j = 0; j < 16; j++) {
            W[j] += upd * sk[c0 + j];
            op += W[j] * sq[c0 + j];
        }
        op += __shfl_xor_sync(0xFFFFFFFFu, op, 1);
        op += __shfl_xor_sync(0xFFFFFFFFu, op, 2);

        if ((tid & 3) == 0)
            g_o[((size_t)(t * BSZ + b)) * INDIM + h * D + row] = op;
        __syncthreads();
    }
}

// ---------------- launch ----------------
extern "C" void kernel_launch(void* const* d_in, const int* in_sizes, int n_in,
                              void* d_out, int out_size)
{
    const float* x      = (const float*)d_in[0];
    const float* gamma  = (const float*)d_in[1];
    const float* beta   = (const float*)d_in[2];
    const float* w_slow = (const float*)d_in[3];
    const float* w_out  = (const float*)d_in[4];
    float* out = (float*)d_out;

    // 1) LayerNorm
    ln_kernel<<<MROWS, 256>>>(x, gamma, beta);

    // 2) qkvb = h @ w_slow   [32768 x 1544]
    {
        dim3 grid((NQKVB + 127) / 128, MROWS / 128);
        sgemm_kernel<<<grid, 256>>>(w_slow, x /*unused*/, nullptr, NQKVB, 0);
    }

    // 3) activations + relayout
    act_kernel<<<MROWS, 256>>>();

    // 4) delta-rule scan
    scan_kernel<<<NBH, 256>>>();

    // 5) out = x + o @ w_out  [32768 x 512]
    {
        dim3 grid(INDIM / 128, MROWS / 128);
        sgemm_kernel<<<grid, 256>>>(w_out, x, out, INDIM, 1);
    }
}

// round 3
// speedup vs baseline: 2.3505x; 2.3505x over previous
#include <cuda_runtime.h>
#include <cuda_fp16.h>
#include <math.h>
#include <stdint.h>

// ---------------- problem constants ----------------
#define SLEN 1024
#define BSZ  32
#define INDIM 512
#define H 8
#define D 64
#define NQKVB (H * (3 * D + 1))   // 1544
#define NQKVB_PAD 1664            // 13 * 128
#define MROWS (SLEN * BSZ)        // 32768
#define NBH   (BSZ * H)           // 256
#define LN_EPS 1e-5f

// ---------------- scratch ----------------
__device__ __half g_hh[(size_t)MROWS * INDIM];         // LN output, fp16
__device__ float  g_qkvb[(size_t)MROWS * NQKVB];       // GEMM1 out, fp32
__device__ float  g_q[(size_t)NBH * SLEN * D];
__device__ float  g_k[(size_t)NBH * SLEN * D];
__device__ float  g_v[(size_t)NBH * SLEN * D];
__device__ float  g_beta[(size_t)NBH * SLEN];
__device__ __half g_oh[(size_t)MROWS * INDIM];         // scan output, fp16
__device__ __half g_wslowT[(size_t)NQKVB_PAD * INDIM]; // [n][k] fp16, pad rows zero
__device__ __half g_woutT[(size_t)INDIM * INDIM];      // [n][k] fp16

// ---------------- transpose + fp16 convert (+zero-pad rows) ----------------
__global__ __launch_bounds__(256)
void transpose_pad_kernel(const float* __restrict__ src, __half* __restrict__ dst,
                          int K, int N, int Npad)
{
    __shared__ float tile[32][33];
    const int n0 = blockIdx.x * 32, k0 = blockIdx.y * 32;
    const int tx = threadIdx.x & 31, ty = threadIdx.x >> 5;  // 32 x 8
    #pragma unroll
    for (int i = ty; i < 32; i += 8) {
        const int n = n0 + tx;
        tile[i][tx] = (n < N) ? src[(size_t)(k0 + i) * N + n] : 0.f;
    }
    __syncthreads();
    #pragma unroll
    for (int i = ty; i < 32; i += 8) {
        const int n = n0 + i;
        if (n < Npad) dst[(size_t)n * K + k0 + tx] = __float2half(tile[tx][i]);
    }
}

// ---------------- LayerNorm -> fp16 ----------------
__global__ __launch_bounds__(256)
void ln_kernel(const float* __restrict__ x, const float* __restrict__ gamma,
               const float* __restrict__ beta)
{
    __shared__ float red[16];
    const int r = blockIdx.x;
    const int tid = threadIdx.x;
    const float* xr = x + (size_t)r * INDIM;
    float v0 = xr[tid];
    float v1 = xr[tid + 256];
    float s = v0 + v1;
    float ss = v0 * v0 + v1 * v1;
    #pragma unroll
    for (int o = 16; o; o >>= 1) {
        s  += __shfl_xor_sync(0xFFFFFFFFu, s, o);
        ss += __shfl_xor_sync(0xFFFFFFFFu, ss, o);
    }
    if ((tid & 31) == 0) { red[tid >> 5] = s; red[8 + (tid >> 5)] = ss; }
    __syncthreads();
    float st = 0.f, sst = 0.f;
    #pragma unroll
    for (int i = 0; i < 8; i++) { st += red[i]; sst += red[8 + i]; }
    const float mu  = st * (1.0f / INDIM);
    const float var = sst * (1.0f / INDIM) - mu * mu;
    const float inv = rsqrtf(var + LN_EPS);
    __half* hr = g_hh + (size_t)r * INDIM;
    hr[tid]       = __float2half((v0 - mu) * inv * gamma[tid]       + beta[tid]);
    hr[tid + 256] = __float2half((v1 - mu) * inv * gamma[tid + 256] + beta[tid + 256]);
}

// ---------------- fp16 mma.sync GEMM ----------------
// C[M,Ncols] = A[M,512](fp16) @ Bt[n][k](fp16)^T (+Res fp32)
// CTA tile 128x128, BK=32, 3-stage cp.async pipeline, 8 warps (2m x 4n), warp tile 64x32.
#define BK 32
#define KT (INDIM / BK)          // 16
#define ROWP 40                  // padded row stride in halfs (80B, 16B-aligned, conflict-free)
#define STAGE_HALFS (128 * ROWP) // 5120 halfs = 10240 B
#define GEMM_SMEM (3 * 2 * STAGE_HALFS * 2)  // 61440 B

__device__ __forceinline__ void load_stage(__half* sm, const __half* __restrict__ g,
                                           int row0, int k0, int tid)
{
    #pragma unroll
    for (int i = 0; i < 2; i++) {
        const int idx = tid + i * 256;
        const int row = idx >> 2;
        const int ch  = (idx & 3) << 3;           // 0,8,16,24 halfs
        const __half* gp = g + (size_t)(row0 + row) * INDIM + (k0 + ch);
        uint32_t dst;
        asm("{ .reg .u64 t; cvta.to.shared.u64 t, %1; cvt.u32.u64 %0, t; }"
            : "=r"(dst) : "l"(sm + row * ROWP + ch));
        asm volatile("cp.async.cg.shared.global [%0], [%1], 16;" :: "r"(dst), "l"(gp));
    }
}

__global__ __launch_bounds__(256)
void gemm_hmma_kernel(const __half* __restrict__ A, const __half* __restrict__ Bt,
                      float* __restrict__ C, const float* __restrict__ Res, int Ncols)
{
    extern __shared__ __half sm[];
    __half* SA = sm;                       // 3 stages
    __half* SB = sm + 3 * STAGE_HALFS;     // 3 stages

    const int tid = threadIdx.x, wid = tid >> 5, lane = tid & 31;
    const int bm = blockIdx.y * 128, bn = blockIdx.x * 128;
    const int wm = (wid >> 2) * 64;        // 0 or 64
    const int wn = (wid & 3) * 32;         // 0,32,64,96
    const int g = lane >> 2, c = lane & 3;

    float acc[4][4][4];
    #pragma unroll
    for (int i = 0; i < 4; i++)
        #pragma unroll
        for (int j = 0; j < 4; j++)
            #pragma unroll
            for (int r = 0; r < 4; r++) acc[i][j][r] = 0.f;

    // prologue: stages 0,1
    load_stage(SA, A, bm, 0, tid);
    load_stage(SB, Bt, bn, 0, tid);
    asm volatile("cp.async.commit_group;");
    load_stage(SA + STAGE_HALFS, A, bm, BK, tid);
    load_stage(SB + STAGE_HALFS, Bt, bn, BK, tid);
    asm volatile("cp.async.commit_group;");

    for (int kt = 0; kt < KT; ++kt) {
        asm volatile("cp.async.wait_group 1;");
        __syncthreads();
        // prefetch stage kt+2 into slot (kt+2)%3 (safe: all warps done with kt-1's slot)
        if (kt + 2 < KT) {
            const int ps = (kt + 2) % 3;
            load_stage(SA + ps * STAGE_HALFS, A, bm, (kt + 2) * BK, tid);
            load_stage(SB + ps * STAGE_HALFS, Bt, bn, (kt + 2) * BK, tid);
        }
        asm volatile("cp.async.commit_group;");

        const __half* sa = SA + (kt % 3) * STAGE_HALFS;
        const __half* sb = SB + (kt % 3) * STAGE_HALFS;
        #pragma unroll
        for (int ks = 0; ks < 2; ks++) {
            const int kb = ks * 16;
            uint32_t af[4][4], bf[4][2];
            #pragma unroll
            for (int im = 0; im < 4; im++) {
                const __half* p = sa + (wm + im * 16 + g) * ROWP + kb + 2 * c;
                af[im][0] = *(const uint32_t*)p;
                af[im][1] = *(const uint32_t*)(p + 8 * ROWP);
                af[im][2] = *(const uint32_t*)(p + 8);
                af[im][3] = *(const uint32_t*)(p + 8 * ROWP + 8);
            }
            #pragma unroll
            for (int in = 0; in < 4; in++) {
                const __half* p = sb + (wn + in * 8 + g) * ROWP + kb + 2 * c;
                bf[in][0] = *(const uint32_t*)p;
                bf[in][1] = *(const uint32_t*)(p + 8);
            }
            #pragma unroll
            for (int im = 0; im < 4; im++)
                #pragma unroll
                for (int in = 0; in < 4; in++)
                    asm volatile(
                        "mma.sync.aligned.m16n8k16.row.col.f32.f16.f16.f32 "
                        "{%0,%1,%2,%3}, {%4,%5,%6,%7}, {%8,%9}, {%0,%1,%2,%3};"
                        : "+f"(acc[im][in][0]), "+f"(acc[im][in][1]),
                          "+f"(acc[im][in][2]), "+f"(acc[im][in][3])
                        : "r"(af[im][0]), "r"(af[im][1]), "r"(af[im][2]), "r"(af[im][3]),
                          "r"(bf[in][0]), "r"(bf[in][1]));
        }
    }

    // epilogue
    #pragma unroll
    for (int im = 0; im < 4; im++) {
        #pragma unroll
        for (int in = 0; in < 4; in++) {
            const int col = bn + wn + in * 8 + 2 * c;
            if (col < Ncols) {
                const int r0 = bm + wm + im * 16 + g;
                float2 v0 = make_float2(acc[im][in][0], acc[im][in][1]);
                float2 v1 = make_float2(acc[im][in][2], acc[im][in][3]);
                if (Res) {
                    const float2 a0 = *(const float2*)(Res + (size_t)r0 * Ncols + col);
                    const float2 a1 = *(const float2*)(Res + (size_t)(r0 + 8) * Ncols + col);
                    v0.x += a0.x; v0.y += a0.y; v1.x += a1.x; v1.y += a1.y;
                }
                *(float2*)(C + (size_t)r0 * Ncols + col) = v0;
                *(float2*)(C + (size_t)(r0 + 8) * Ncols + col) = v1;
            }
        }
    }
}

// ---------------- activation + relayout ----------------
__device__ __forceinline__ float elu_p1(float x) {
    return x > 0.f ? x + 1.0f : expf(x);
}

__global__ __launch_bounds__(256)
void act_kernel()
{
    const int r = blockIdx.x;
    const int w = threadIdx.x >> 5;
    const int lane = threadIdx.x & 31;
    const int t = r >> 5, b = r & 31;
    const int bh = b * H + w;
    const float* p = g_qkvb + (size_t)r * NQKVB + w * (3 * D + 1);
    const size_t ob = ((size_t)bh * SLEN + t) * D;

    float q0 = elu_p1(p[lane]);
    float q1 = elu_p1(p[lane + 32]);
    float s = q0 + q1;
    #pragma unroll
    for (int o = 16; o; o >>= 1) s += __shfl_xor_sync(0xFFFFFFFFu, s, o);
    float inv = 1.0f / s;
    g_q[ob + lane] = q0 * inv;
    g_q[ob + lane + 32] = q1 * inv;

    float k0 = elu_p1(p[D + lane]);
    float k1 = elu_p1(p[D + lane + 32]);
    s = k0 + k1;
    #pragma unroll
    for (int o = 16; o; o >>= 1) s += __shfl_xor_sync(0xFFFFFFFFu, s, o);
    inv = 1.0f / s;
    g_k[ob + lane] = k0 * inv;
    g_k[ob + lane + 32] = k1 * inv;

    g_v[ob + lane] = p[2 * D + lane];
    g_v[ob + lane + 32] = p[2 * D + lane + 32];

    if (lane == 0)
        g_beta[(size_t)bh * SLEN + t] = 1.0f / (1.0f + expf(-p[3 * D]));
}

// ---------------- delta-rule scan (pipelined, 1 barrier/step) ----------------
__global__ __launch_bounds__(256)
void scan_kernel()
{
    const int bh = blockIdx.x;
    const int b = bh >> 3, h = bh & 7;
    const int tid = threadIdx.x;
    const int row = tid >> 2;
    const int c0 = (tid & 3) << 4;

    __shared__ float sk[2][D], sv[2][D], sq[2][D];
    __shared__ float sbet[2];

    const size_t base0 = (size_t)bh * SLEN * D;
    const int role = tid >> 6;       // 0:k 1:v 2:q 3:(beta on tid==192)
    const int rl = tid & 63;

    // fill buffer 0 with t=0; preA holds t=1
    float preA = 0.f;
    if (role == 0) { sk[0][rl] = g_k[base0 + rl]; preA = g_k[base0 + D + rl]; }
    else if (role == 1) { sv[0][rl] = g_v[base0 + rl]; preA = g_v[base0 + D + rl]; }
    else if (role == 2) { sq[0][rl] = g_q[base0 + rl]; preA = g_q[base0 + D + rl]; }
    else if (tid == 192) { sbet[0] = g_beta[(size_t)bh * SLEN]; preA = g_beta[(size_t)bh * SLEN + 1]; }
    __syncthreads();

    float W[16];
    #pragma unroll
    for (int j = 0; j < 16; j++) W[j] = 0.f;

    for (int t = 0; t < SLEN; t++) {
        const int cur = t & 1, nxt = cur ^ 1;

        // prefetch t+2 into regs (consumed at end of next iter -> ~1.5 iters of cover)
        float preB = 0.f;
        if (t + 2 < SLEN) {
            const size_t base2 = base0 + (size_t)(t + 2) * D;
            if (role == 0) preB = g_k[base2 + rl];
            else if (role == 1) preB = g_v[base2 + rl];
            else if (role == 2) preB = g_q[base2 + rl];
            else if (tid == 192) preB = g_beta[(size_t)bh * SLEN + t + 2];
        }

        const float bt = sbet[cur];
        float kk[16], qq[16];
        #pragma unroll
        for (int j4 = 0; j4 < 4; j4++) {
            *(float4*)&kk[j4 * 4] = *(const float4*)&sk[cur][c0 + j4 * 4];
            *(float4*)&qq[j4 * 4] = *(const float4*)&sq[cur][c0 + j4 * 4];
        }

        float vold = 0.f;
        #pragma unroll
        for (int j = 0; j < 16; j++) vold += W[j] * kk[j];
        vold += __shfl_xor_sync(0xFFFFFFFFu, vold, 1);
        vold += __shfl_xor_sync(0xFFFFFFFFu, vold, 2);

        const float upd = bt * (sv[cur][row] - vold);

        float op = 0.f;
        #pragma unroll
        for (int j = 0; j < 16; j++) {
            W[j] += upd * kk[j];
            op += W[j] * qq[j];
        }
        op += __shfl_xor_sync(0xFFFFFFFFu, op, 1);
        op += __shfl_xor_sync(0xFFFFFFFFu, op, 2);

        if ((tid & 3) == 0)
            g_oh[((size_t)(t * BSZ + b)) * INDIM + h * D + row] = __float2half(op);

        // publish t+1 into the other buffer
        if (t + 1 < SLEN) {
            if (role == 0) sk[nxt][rl] = preA;
            else if (role == 1) sv[nxt][rl] = preA;
            else if (role == 2) sq[nxt][rl] = preA;
            else if (tid == 192) sbet[nxt] = preA;
        }
        __syncthreads();
        preA = preB;
    }
}

// ---------------- launch ----------------
extern "C" void kernel_launch(void* const* d_in, const int* in_sizes, int n_in,
                              void* d_out, int out_size)
{
    const float* x      = (const float*)d_in[0];
    const float* gamma  = (const float*)d_in[1];
    const float* beta   = (const float*)d_in[2];
    const float* w_slow = (const float*)d_in[3];
    const float* w_out  = (const float*)d_in[4];
    float* out = (float*)d_out;

    static bool attr_set = false;
    if (!attr_set) {
        cudaFuncSetAttribute(gemm_hmma_kernel, cudaFuncAttributeMaxDynamicSharedMemorySize, GEMM_SMEM);
        attr_set = true;
    }

    __half* wslowT; cudaGetSymbolAddress((void**)&wslowT, g_wslowT);
    __half* woutT;  cudaGetSymbolAddress((void**)&woutT,  g_woutT);
    __half* hbuf;   cudaGetSymbolAddress((void**)&hbuf,   g_hh);
    float*  qkvb;   cudaGetSymbolAddress((void**)&qkvb,   g_qkvb);
    __half* obuf;   cudaGetSymbolAddress((void**)&obuf,   g_oh);

    // 0) weight transposes (n-major fp16 B)
    {
        dim3 blk(256);
        dim3 g1(NQKVB_PAD / 32, INDIM / 32);
        transpose_pad_kernel<<<g1, blk>>>(w_slow, wslowT, INDIM, NQKVB, NQKVB_PAD);
        dim3 g2(INDIM / 32, INDIM / 32);
        transpose_pad_kernel<<<g2, blk>>>(w_out, woutT, INDIM, INDIM, INDIM);
    }

    // 1) LayerNorm
    ln_kernel<<<MROWS, 256>>>(x, gamma, beta);

    // 2) qkvb = h @ w_slow
    {
        dim3 grid(NQKVB_PAD / 128, MROWS / 128);
        gemm_hmma_kernel<<<grid, 256, GEMM_SMEM>>>(hbuf, wslowT, qkvb, nullptr, NQKVB);
    }

    // 3) activations + relayout
    act_kernel<<<MROWS, 256>>>();

    // 4) delta-rule scan
    scan_kernel<<<NBH, 256>>>();

    // 5) out = x + o @ w_out
    {
        dim3 grid(INDIM / 128, MROWS / 128);
        gemm_hmma_kernel<<<grid, 256, GEMM_SMEM>>>(obuf, woutT, out, x, INDIM);
    }
}